// round 6
// baseline (speedup 1.0000x reference)
#include <cuda_runtime.h>
#include <math.h>

#define N_STATIONS 100000
#define N_TIME     1000
#define K_NEIGH    8
#define SMOOTH_C   0.2f
#define KEEP_C     0.8f
#define N_COMP     4
#define COEFF_STRIDE 20   // 10 coeffs, duplicated {k,k} pairs = 5 float4
#define TABLE_STRIDE 12   // t, s0..s3, c0..c3, pad x3
#define CHUNKS     250    // 1000 times / 4 per thread
#define GRID_EVAL  592    // 148 SMs x 4 CTAs: exactly one wave, persistent
#define TILE       ((N_STATIONS + GRID_EVAL - 1) / GRID_EVAL)   // 169

// Scratch (no cudaMalloc allowed)
__device__ float g_coeff[N_STATIONS * COEFF_STRIDE];
__device__ float g_table[N_TIME * TABLE_STRIDE];

typedef unsigned long long u64;

// ---- packed f32x2 helpers ---------------------------------------------------
__device__ __forceinline__ u64 pk2(float lo, float hi) {
    u64 r; asm("mov.b64 %0, {%1, %2};" : "=l"(r) : "f"(lo), "f"(hi)); return r;
}
__device__ __forceinline__ u64 fma2(u64 a, u64 b, u64 c) {
    u64 d; asm("fma.rn.f32x2 %0, %1, %2, %3;" : "=l"(d) : "l"(a), "l"(b), "l"(c)); return d;
}
__device__ __forceinline__ u64 mul2(u64 a, u64 b) {
    u64 d; asm("mul.rn.f32x2 %0, %1, %2;" : "=l"(d) : "l"(a), "l"(b)); return d;
}
__device__ __forceinline__ u64 add2(u64 a, u64 b) {
    u64 d; asm("add.rn.f32x2 %0, %1, %2;" : "=l"(d) : "l"(a), "l"(b)); return d;
}
__device__ __forceinline__ void stcs2(void* p, u64 a, u64 b) {
    asm volatile("st.global.cs.v2.u64 [%0], {%1, %2};" :: "l"(p), "l"(a), "l"(b) : "memory");
}

// ---------------------------------------------------------------------------
// Kernel 1: smoothing, TWO threads per station (even lane: neighbors 0-3,
// odd lane: neighbors 4-7), partials combined via shfl_xor(1). Each lane then
// finalizes 2 of the 4 seasonal components. First 1000 global threads also
// build the time table.
// ---------------------------------------------------------------------------
__global__ void __launch_bounds__(256) smooth_kernel(
    const float* __restrict__ off,
    const float* __restrict__ trend,
    const float* __restrict__ amps,
    const float* __restrict__ phases,
    const int*   __restrict__ nidx,
    const float* __restrict__ nw,
    const float* __restrict__ time_vector,
    const float* __restrict__ periods)
{
    const int g = blockIdx.x * blockDim.x + threadIdx.x;

    // fused time-table build (accurate sincosf; args < ~130 rad)
    if (g < N_TIME) {
        float t = time_vector[g];
        float e[TABLE_STRIDE];
        e[0] = t;
#pragma unroll
        for (int i = 0; i < N_COMP; ++i) {
            float w = 6.2831853071795864769f / periods[i];
            float sv, cv;
            sincosf(w * t, &sv, &cv);
            e[1 + i] = sv;
            e[5 + i] = cv;
        }
        e[9] = 0.f; e[10] = 0.f; e[11] = 0.f;
        float4* dst = reinterpret_cast<float4*>(g_table + g * TABLE_STRIDE);
        dst[0] = make_float4(e[0], e[1], e[2],  e[3]);
        dst[1] = make_float4(e[4], e[5], e[6],  e[7]);
        dst[2] = make_float4(e[8], e[9], e[10], e[11]);
    }

    const int st   = g >> 1;
    const int half = g & 1;
    if (st >= N_STATIONS) return;

    // this lane's 4 neighbors
    int4   ni = reinterpret_cast<const int4*>(nidx + st * K_NEIGH)[half];
    float4 wf = reinterpret_cast<const float4*>(nw   + st * K_NEIGH)[half];
    int   nbv[4] = {ni.x, ni.y, ni.z, ni.w};
    float wv [4] = {wf.x, wf.y, wf.z, wf.w};

    float avg_amp[N_COMP] = {0.f, 0.f, 0.f, 0.f};
    float avg_re [N_COMP] = {0.f, 0.f, 0.f, 0.f};
    float avg_im [N_COMP] = {0.f, 0.f, 0.f, 0.f};

#pragma unroll
    for (int k = 0; k < 4; ++k) {
        int   nb = nbv[k];
        float w  = wv[k];
        const float4 na = *reinterpret_cast<const float4*>(amps   + nb * 4);
        const float4 np = *reinterpret_cast<const float4*>(phases + nb * 4);
        float av[4] = {na.x, na.y, na.z, na.w};
        float pv[4] = {np.x, np.y, np.z, np.w};
#pragma unroll
        for (int i = 0; i < N_COMP; ++i) {
            avg_amp[i] = fmaf(w, av[i], avg_amp[i]);
            float sp, cp;
            __sincosf(pv[i], &sp, &cp);
            avg_re[i] = fmaf(w, cp, avg_re[i]);
            avg_im[i] = fmaf(w, sp, avg_im[i]);
        }
    }

    // combine with partner lane (even/odd pair lives in the same warp)
    const unsigned mask = 0xFFFFFFFFu;
#pragma unroll
    for (int i = 0; i < N_COMP; ++i) {
        avg_amp[i] += __shfl_xor_sync(mask, avg_amp[i], 1);
        avg_re [i] += __shfl_xor_sync(mask, avg_re [i], 1);
        avg_im [i] += __shfl_xor_sync(mask, avg_im [i], 1);
    }

    // this lane finalizes components c0, c0+1
    const int c0 = half * 2;
    const float2 oa = *reinterpret_cast<const float2*>(amps   + st * 4 + c0);
    const float2 op = *reinterpret_cast<const float2*>(phases + st * 4 + c0);
    float a0[2] = {oa.x, oa.y};
    float p0[2] = {op.x, op.y};

    float A[2], B[2];
#pragma unroll
    for (int i = 0; i < 2; ++i) {
        float amp_s = KEEP_C * a0[i] + SMOOTH_C * avg_amp[c0 + i];
        float sp, cp;
        __sincosf(p0[i], &sp, &cp);
        float mr = KEEP_C * cp + SMOOTH_C * avg_re[c0 + i];
        float mi = KEEP_C * sp + SMOOTH_C * avg_im[c0 + i];
        float inv = rsqrtf(fmaxf(mr * mr + mi * mi, 1e-30f));
        A[i] = amp_s * mr * inv;
        B[i] = amp_s * mi * inv;
    }

    float4* dst = reinterpret_cast<float4*>(g_coeff + st * COEFF_STRIDE);
    if (half == 0) {
        float o  = off[st];
        float tr = trend[st];
        dst[0] = make_float4(o,    o,    tr,   tr);
        dst[1] = make_float4(A[0], A[0], A[1], A[1]);   // A0, A1
        dst[3] = make_float4(B[0], B[0], B[1], B[1]);   // B0, B1
    } else {
        dst[2] = make_float4(A[0], A[0], A[1], A[1]);   // A2, A3
        dst[4] = make_float4(B[0], B[0], B[1], B[1]);   // B2, B3
    }
}

// ---------------------------------------------------------------------------
// Kernel 2: persistent evaluation — exactly GRID_EVAL CTAs (one full 4-CTA
// wave). Each CTA stages its 169-station tile's coefficients in smem once,
// then evaluates: broadcast LDS.128 coefficients, table in regs,
// tree-structured FMA2 (3 chains), streaming STG.128.
// ---------------------------------------------------------------------------
__global__ void __launch_bounds__(256, 4) eval_kernel(float* __restrict__ out)
{
    __shared__ float4 s_coeff[TILE * 5];   // 13520 B

    const int  col    = threadIdx.x;       // chunks 0..249 real
    const bool active = (col < CHUNKS);

    const int s_base = blockIdx.x * TILE;
    const int ns     = min(TILE, N_STATIONS - s_base);
    if (ns <= 0) return;

    // cooperative coalesced coefficient staging
    {
        const float4* gsrc = reinterpret_cast<const float4*>(g_coeff) + (size_t)s_base * 5;
        const int total_f4 = ns * 5;
        for (int i = threadIdx.x; i < total_f4; i += 256)
            s_coeff[i] = gsrc[i];
    }

    // per-thread time table in registers
    u64 tt2[2];
    u64 ss2[2][4];
    u64 cc2[2][4];
    if (active) {
#pragma unroll
        for (int h = 0; h < 2; ++h) {
            const float* tpA = g_table + (col * 4 + 2 * h)     * TABLE_STRIDE;
            const float* tpB = g_table + (col * 4 + 2 * h + 1) * TABLE_STRIDE;
            float4 a0 = reinterpret_cast<const float4*>(tpA)[0];
            float4 a1 = reinterpret_cast<const float4*>(tpA)[1];
            float4 a2 = reinterpret_cast<const float4*>(tpA)[2];
            float4 b0 = reinterpret_cast<const float4*>(tpB)[0];
            float4 b1 = reinterpret_cast<const float4*>(tpB)[1];
            float4 b2 = reinterpret_cast<const float4*>(tpB)[2];
            tt2[h]    = pk2(a0.x, b0.x);
            ss2[h][0] = pk2(a0.y, b0.y);
            ss2[h][1] = pk2(a0.z, b0.z);
            ss2[h][2] = pk2(a0.w, b0.w);
            ss2[h][3] = pk2(a1.x, b1.x);
            cc2[h][0] = pk2(a1.y, b1.y);
            cc2[h][1] = pk2(a1.z, b1.z);
            cc2[h][2] = pk2(a1.w, b1.w);
            cc2[h][3] = pk2(a2.x, b2.x);
        }
    }

    __syncthreads();

    for (int j = 0; j < ns; ++j) {
        // broadcast LDS.128 x5 — all lanes read the same address
        const ulonglong2* cp = reinterpret_cast<const ulonglong2*>(&s_coeff[j * 5]);
        ulonglong2 x0 = cp[0];  // {off,off},{trend,trend}
        ulonglong2 x1 = cp[1];  // {A0,A0},{A1,A1}
        ulonglong2 x2 = cp[2];  // {A2,A2},{A3,A3}
        ulonglong2 x3 = cp[3];  // {B0,B0},{B1,B1}
        ulonglong2 x4 = cp[4];  // {B2,B2},{B3,B3}

        if (active) {
            u64 r[2];
#pragma unroll
            for (int h = 0; h < 2; ++h) {
                u64 p0 = fma2(x0.y, tt2[h],    x0.x);    // off + trend*t
                u64 p1 = mul2(x1.x, ss2[h][0]);          // A0*s0
                u64 p2 = mul2(x1.y, ss2[h][1]);          // A1*s1
                p0 = fma2(x2.x, ss2[h][2], p0);          // +A2*s2
                p1 = fma2(x2.y, ss2[h][3], p1);          // +A3*s3
                p2 = fma2(x3.x, cc2[h][0], p2);          // +B0*c0
                p0 = fma2(x3.y, cc2[h][1], p0);          // +B1*c1
                p1 = fma2(x4.x, cc2[h][2], p1);          // +B2*c2
                p2 = fma2(x4.y, cc2[h][3], p2);          // +B3*c3
                r[h] = add2(p0, add2(p1, p2));
            }
            stcs2(out + (size_t)(s_base + j) * N_TIME + col * 4, r[0], r[1]);
        }
    }
}

// ---------------------------------------------------------------------------
extern "C" void kernel_launch(void* const* d_in, const int* in_sizes, int n_in,
                              void* d_out, int out_size)
{
    const float* time_vector = (const float*)d_in[0];
    const float* off         = (const float*)d_in[1];
    const float* trend       = (const float*)d_in[2];
    const float* amps        = (const float*)d_in[3];
    const float* phases      = (const float*)d_in[4];
    const int*   nidx        = (const int*)  d_in[5];
    const float* nw          = (const float*)d_in[6];
    const float* periods     = (const float*)d_in[7];
    float* out = (float*)d_out;

    smooth_kernel<<<(2 * N_STATIONS + 255) / 256, 256>>>(
        off, trend, amps, phases, nidx, nw, time_vector, periods);
    eval_kernel<<<GRID_EVAL, 256>>>(out);
}

// round 7
// speedup vs baseline: 1.0294x; 1.0294x over previous
#include <cuda_runtime.h>
#include <math.h>
#include <stdint.h>

#define N_STATIONS 100000
#define N_TIME     1000
#define K_NEIGH    8
#define SMOOTH_C   0.2f
#define KEEP_C     0.8f
#define N_COMP     4
#define TABLE_STRIDE 12   // t, s0..s3, c0..c3, pad x3
#define CHUNKS     250    // 1000 times / 4 per thread
#define GRID_EVAL  592    // 148 SMs x 4 CTAs, one full wave
#define TILE       169    // stations per block (592*169 = 100048 >= 100000)
#define SC         64     // stations per pipeline chunk (4 threads/station)

// Scratch (no cudaMalloc allowed)
__device__ float g_table[N_TIME * TABLE_STRIDE];

typedef unsigned long long u64;

// ---- packed f32x2 helpers ---------------------------------------------------
__device__ __forceinline__ u64 pk2(float lo, float hi) {
    u64 r; asm("mov.b64 %0, {%1, %2};" : "=l"(r) : "f"(lo), "f"(hi)); return r;
}
__device__ __forceinline__ u64 fma2(u64 a, u64 b, u64 c) {
    u64 d; asm("fma.rn.f32x2 %0, %1, %2, %3;" : "=l"(d) : "l"(a), "l"(b), "l"(c)); return d;
}
__device__ __forceinline__ u64 mul2(u64 a, u64 b) {
    u64 d; asm("mul.rn.f32x2 %0, %1, %2;" : "=l"(d) : "l"(a), "l"(b)); return d;
}
__device__ __forceinline__ u64 add2(u64 a, u64 b) {
    u64 d; asm("add.rn.f32x2 %0, %1, %2;" : "=l"(d) : "l"(a), "l"(b)); return d;
}
__device__ __forceinline__ void stcs2(void* p, u64 a, u64 b) {
    asm volatile("st.global.cs.v2.u64 [%0], {%1, %2};" :: "l"(p), "l"(a), "l"(b) : "memory");
}
__device__ __forceinline__ void cpasync16(uint32_t dst, const void* src) {
    asm volatile("cp.async.ca.shared.global [%0], [%1], 16;" :: "r"(dst), "l"(src));
}
#define CP_COMMIT() asm volatile("cp.async.commit_group;" ::: "memory")
#define CP_WAIT0()  asm volatile("cp.async.wait_group 0;"  ::: "memory")

// ---------------------------------------------------------------------------
// Kernel 1 (tiny): time table — accurate sincosf.
// ---------------------------------------------------------------------------
__global__ void table_kernel(const float* __restrict__ time_vector,
                             const float* __restrict__ periods)
{
    int j = blockIdx.x * blockDim.x + threadIdx.x;
    if (j >= N_TIME) return;
    float t = time_vector[j];
    float e[TABLE_STRIDE];
    e[0] = t;
#pragma unroll
    for (int i = 0; i < N_COMP; ++i) {
        float w = 6.2831853071795864769f / periods[i];
        float sv, cv;
        sincosf(w * t, &sv, &cv);
        e[1 + i] = sv;
        e[5 + i] = cv;
    }
    e[9] = 0.f; e[10] = 0.f; e[11] = 0.f;
    float4* dst = reinterpret_cast<float4*>(g_table + j * TABLE_STRIDE);
    dst[0] = make_float4(e[0], e[1], e[2],  e[3]);
    dst[1] = make_float4(e[4], e[5], e[6],  e[7]);
    dst[2] = make_float4(e[8], e[9], e[10], e[11]);
}

// ---------------------------------------------------------------------------
// Kernel 2: fused persistent smooth+eval, software-pipelined.
//  - 592 CTAs (one wave). Each owns TILE stations, processed in SC-chunks.
//  - Chunk gathers staged via cp.async into smem (no regs), math after the
//    current chunk's evaluation has been issued -> gather latency hidden.
//  - Smoothing: 4 threads/station (2 neighbors each), shfl_xor(1),(2) combine,
//    sub-thread c finalizes component c. No atan2 (re/im normalization).
//  - Eval: broadcast LDS.128 coefficients, table in regs, FMA2 tree chains,
//    streaming STG.128.
// ---------------------------------------------------------------------------
__global__ void __launch_bounds__(256, 4) fused_kernel(
    float* __restrict__ out,
    const float* __restrict__ off,
    const float* __restrict__ trend,
    const float* __restrict__ amps,
    const float* __restrict__ phases,
    const int*   __restrict__ nidx,
    const float* __restrict__ nw)
{
    __shared__ float4 s_coeff[2][SC * 5];     // 10240 B (double buffer)
    __shared__ float4 s_stage[SC * K_NEIGH * 2]; // 16384 B: per nbr {amps16B, phases16B}

    const int  tid    = threadIdx.x;
    const int  col    = tid;                 // chunks 0..249 real
    const bool active = (col < CHUNKS);
    const int  lst    = tid >> 2;            // local station within chunk (0..63)
    const int  sub    = tid & 3;             // component / neighbor-pair id

    const int s_base = blockIdx.x * TILE;
    const int ns     = min(TILE, N_STATIONS - s_base);   // >= 1 for all 592 blocks
    const int nch    = (ns + SC - 1) / SC;

    const uint32_t stage_b =
        (uint32_t)__cvta_generic_to_shared(&s_stage[0]);

    // ---- helpers as lambdas --------------------------------------------------
    // Issue gathers for chunk c (all 256 threads; station clamped for tail).
    float2 wt;   // this thread's 2 neighbor weights for the staged chunk
    auto issue_chunk = [&](int c) {
        int stc = min(c * SC + lst, ns - 1);
        int st  = s_base + stc;
        int2   id = *reinterpret_cast<const int2*>(nidx + st * K_NEIGH + sub * 2);
        wt        = *reinterpret_cast<const float2*>(nw  + st * K_NEIGH + sub * 2);
        uint32_t d = stage_b + (uint32_t)(lst * K_NEIGH + sub * 2) * 32u;
        cpasync16(d +  0, amps   + (size_t)id.x * 4);
        cpasync16(d + 16, phases + (size_t)id.x * 4);
        cpasync16(d + 32, amps   + (size_t)id.y * 4);
        cpasync16(d + 48, phases + (size_t)id.y * 4);
    };

    // Consume staged gathers for chunk c -> write coefficient buffer `buf`.
    auto math_chunk = [&](int c, int buf) {
        int stc = min(c * SC + lst, ns - 1);
        int st  = s_base + stc;

        float aa[N_COMP] = {0.f, 0.f, 0.f, 0.f};
        float re[N_COMP] = {0.f, 0.f, 0.f, 0.f};
        float im[N_COMP] = {0.f, 0.f, 0.f, 0.f};
#pragma unroll
        for (int n = 0; n < 2; ++n) {
            float4 na = s_stage[(lst * K_NEIGH + sub * 2 + n) * 2 + 0];
            float4 np = s_stage[(lst * K_NEIGH + sub * 2 + n) * 2 + 1];
            float  w  = (n == 0) ? wt.x : wt.y;
            float av[4] = {na.x, na.y, na.z, na.w};
            float pv[4] = {np.x, np.y, np.z, np.w};
#pragma unroll
            for (int i = 0; i < N_COMP; ++i) {
                aa[i] = fmaf(w, av[i], aa[i]);
                float sp, cp;
                __sincosf(pv[i], &sp, &cp);
                re[i] = fmaf(w, cp, re[i]);
                im[i] = fmaf(w, sp, im[i]);
            }
        }
        const unsigned m = 0xFFFFFFFFu;   // no divergence here: all threads run math
#pragma unroll
        for (int i = 0; i < N_COMP; ++i) {
            aa[i] += __shfl_xor_sync(m, aa[i], 1);
            re[i] += __shfl_xor_sync(m, re[i], 1);
            im[i] += __shfl_xor_sync(m, im[i], 1);
            aa[i] += __shfl_xor_sync(m, aa[i], 2);
            re[i] += __shfl_xor_sync(m, re[i], 2);
            im[i] += __shfl_xor_sync(m, im[i], 2);
        }
        // this sub-thread finalizes component `sub`
        float a0 = amps  [st * 4 + sub];
        float p0 = phases[st * 4 + sub];
        float amp_s = KEEP_C * a0 + SMOOTH_C * aa[sub];
        float sp, cp;
        __sincosf(p0, &sp, &cp);
        float mr = KEEP_C * cp + SMOOTH_C * re[sub];
        float mi = KEEP_C * sp + SMOOTH_C * im[sub];
        float inv = rsqrtf(fmaxf(mr * mr + mi * mi, 1e-30f));
        float A = amp_s * mr * inv;
        float B = amp_s * mi * inv;

        if (c * SC + lst < ns) {
            float* base = reinterpret_cast<float*>(&s_coeff[buf][0]) + lst * 20;
            if (sub == 0) {
                float o  = off[st];
                float tr = trend[st];
                base[0] = o;  base[1] = o;
                base[2] = tr; base[3] = tr;
            }
            *reinterpret_cast<float2*>(base + 4  + 2 * sub) = make_float2(A, A);
            *reinterpret_cast<float2*>(base + 12 + 2 * sub) = make_float2(B, B);
        }
    };

    // ---- prologue: stage+math chunk 0, load table regs ------------------------
    issue_chunk(0);
    CP_COMMIT();

    u64 tt2[2];
    u64 ss2[2][4];
    u64 cc2[2][4];
    if (active) {
#pragma unroll
        for (int h = 0; h < 2; ++h) {
            const float* tpA = g_table + (col * 4 + 2 * h)     * TABLE_STRIDE;
            const float* tpB = g_table + (col * 4 + 2 * h + 1) * TABLE_STRIDE;
            float4 a0 = reinterpret_cast<const float4*>(tpA)[0];
            float4 a1 = reinterpret_cast<const float4*>(tpA)[1];
            float4 a2 = reinterpret_cast<const float4*>(tpA)[2];
            float4 b0 = reinterpret_cast<const float4*>(tpB)[0];
            float4 b1 = reinterpret_cast<const float4*>(tpB)[1];
            float4 b2 = reinterpret_cast<const float4*>(tpB)[2];
            tt2[h]    = pk2(a0.x, b0.x);
            ss2[h][0] = pk2(a0.y, b0.y);
            ss2[h][1] = pk2(a0.z, b0.z);
            ss2[h][2] = pk2(a0.w, b0.w);
            ss2[h][3] = pk2(a1.x, b1.x);
            cc2[h][0] = pk2(a1.y, b1.y);
            cc2[h][1] = pk2(a1.z, b1.z);
            cc2[h][2] = pk2(a1.w, b1.w);
            cc2[h][3] = pk2(a2.x, b2.x);
        }
    }

    CP_WAIT0();
    math_chunk(0, 0);
    __syncthreads();

    // ---- pipelined main loop ---------------------------------------------------
    int buf = 0;
    for (int c = 0; c < nch; ++c) {
        const int cbase = c * SC;
        const int cns   = min(SC, ns - cbase);
        const bool have_next = (c + 1 < nch);

        if (have_next) {
            issue_chunk(c + 1);
            CP_COMMIT();
        }

        // evaluate chunk c from s_coeff[buf]
        const float* cfb = reinterpret_cast<const float*>(&s_coeff[buf][0]);
        for (int j = 0; j < cns; ++j) {
            const ulonglong2* cp =
                reinterpret_cast<const ulonglong2*>(cfb + j * 20);
            ulonglong2 x0 = cp[0];
            ulonglong2 x1 = cp[1];
            ulonglong2 x2 = cp[2];
            ulonglong2 x3 = cp[3];
            ulonglong2 x4 = cp[4];
            if (active) {
                u64 r[2];
#pragma unroll
                for (int h = 0; h < 2; ++h) {
                    u64 p0 = fma2(x0.y, tt2[h],    x0.x);
                    u64 p1 = mul2(x1.x, ss2[h][0]);
                    u64 p2 = mul2(x1.y, ss2[h][1]);
                    p0 = fma2(x2.x, ss2[h][2], p0);
                    p1 = fma2(x2.y, ss2[h][3], p1);
                    p2 = fma2(x3.x, cc2[h][0], p2);
                    p0 = fma2(x3.y, cc2[h][1], p0);
                    p1 = fma2(x4.x, cc2[h][2], p1);
                    p2 = fma2(x4.y, cc2[h][3], p2);
                    r[h] = add2(p0, add2(p1, p2));
                }
                stcs2(out + (size_t)(s_base + cbase + j) * N_TIME + col * 4,
                      r[0], r[1]);
            }
        }

        if (have_next) {
            CP_WAIT0();
            math_chunk(c + 1, buf ^ 1);
        }
        __syncthreads();
        buf ^= 1;
    }
}

// ---------------------------------------------------------------------------
extern "C" void kernel_launch(void* const* d_in, const int* in_sizes, int n_in,
                              void* d_out, int out_size)
{
    const float* time_vector = (const float*)d_in[0];
    const float* off         = (const float*)d_in[1];
    const float* trend       = (const float*)d_in[2];
    const float* amps        = (const float*)d_in[3];
    const float* phases      = (const float*)d_in[4];
    const int*   nidx        = (const int*)  d_in[5];
    const float* nw          = (const float*)d_in[6];
    const float* periods     = (const float*)d_in[7];
    float* out = (float*)d_out;

    table_kernel<<<(N_TIME + 255) / 256, 256>>>(time_vector, periods);
    fused_kernel<<<GRID_EVAL, 256>>>(out, off, trend, amps, phases, nidx, nw);
}